// round 16
// baseline (speedup 1.0000x reference)
#include <cuda_runtime.h>
#include <cuda_bf16.h>
#include <math.h>

#define NU 50000
#define NI 40000
#define NN 90000
#define D  64
#define EH 500000
#define E  1000000
#define OD 192

typedef unsigned int uint;

// ------------------- scratch (static device globals; no allocation) -------------------
__device__ int   g_is64;
__device__ int   g_src[E];
__device__ int   g_dst[E];
__device__ int   g_degG[NN];
__device__ int   g_offG[NN];
__device__ int   g_curG[NN];
__device__ int   g_bsum[128];
__device__ int   g_csrG_src[E];
__device__ float g_e[2 * E];
__device__ float g_alpha[2 * E];
__device__ float g_wc[E];
__device__ __align__(16) float g_xm[2 * NN * D];
__device__ __align__(16) float g_hx[2 * NN * D];

__device__ __forceinline__ float lrelu(float v) { return v >= 0.f ? v : 0.01f * v; }
static inline int divup(int a, int b) { return (a + b - 1) / b; }

// ------------------- tensor helpers -------------------
__device__ __forceinline__ uint smem_u32(const void* p) {
    return (uint)__cvta_generic_to_shared(p);
}
__device__ __forceinline__ void ldsm4(uint& r0, uint& r1, uint& r2, uint& r3, uint addr) {
    asm volatile("ldmatrix.sync.aligned.m8n8.x4.shared.b16 {%0,%1,%2,%3},[%4];"
        : "=r"(r0), "=r"(r1), "=r"(r2), "=r"(r3) : "r"(addr));
}
__device__ __forceinline__ void ldsm4t(uint& r0, uint& r1, uint& r2, uint& r3, uint addr) {
    asm volatile("ldmatrix.sync.aligned.m8n8.x4.trans.shared.b16 {%0,%1,%2,%3},[%4];"
        : "=r"(r0), "=r"(r1), "=r"(r2), "=r"(r3) : "r"(addr));
}
__device__ __forceinline__ void mma_bf16(float* c, const uint* a, const uint* b) {
    asm volatile("mma.sync.aligned.m16n8k16.row.col.f32.bf16.bf16.f32 "
        "{%0,%1,%2,%3},{%4,%5,%6,%7},{%8,%9},{%0,%1,%2,%3};"
        : "+f"(c[0]), "+f"(c[1]), "+f"(c[2]), "+f"(c[3])
        : "r"(a[0]), "r"(a[1]), "r"(a[2]), "r"(a[3]), "r"(b[0]), "r"(b[1]));
}
__device__ __forceinline__ void cvt_split(float v, __nv_bfloat16& h, __nv_bfloat16& l) {
    h = __float2bfloat16_rn(v);
    l = __float2bfloat16_rn(v - __bfloat162float(h));
}

// ------------------- graph construction -------------------
// zero degrees; block 0 warp 0 also sniffs the edge dtype.
__global__ void k_zero_sniff(const int* __restrict__ ei32) {
    int i = blockIdx.x * blockDim.x + threadIdx.x;
    if (i < NN) g_degG[i] = 0;
    if (blockIdx.x == 0 && threadIdx.x < 32) {
        int lane = threadIdx.x;
        int nz = 0;
        for (int k = lane; k < 512; k += 32)
            if (ei32[2 * k + 1] != 0) nz++;
        #pragma unroll
        for (int o = 16; o; o >>= 1) nz += __shfl_xor_sync(0xffffffffu, nz, o);
        if (lane == 0) g_is64 = (nz == 0) ? 1 : 0;
    }
}

__global__ void k_build(const void* __restrict__ eiRaw) {
    int i = blockIdx.x * blockDim.x + threadIdx.x;
    if (i >= E) return;
    int s, d;
    if (g_is64) {
        const long long* e64 = (const long long*)eiRaw;
        s = (int)e64[i];
        d = (int)e64[E + i];
    } else {
        const int* e32 = (const int*)eiRaw;
        s = e32[i];
        d = e32[E + i];
    }
    if ((unsigned)s >= NN) s = 0;
    if ((unsigned)d >= NN) d = 0;
    g_src[i] = s;
    g_dst[i] = d;
    atomicAdd(&g_degG[d], 1);
}

__global__ void k_scan1() {
    __shared__ int sh[1024];
    int t = threadIdx.x;
    int i = blockIdx.x * 1024 + t;
    int v = (i < NN) ? g_degG[i] : 0;
    sh[t] = v;
    __syncthreads();
    for (int st = 1; st < 1024; st <<= 1) {
        int x = (t >= st) ? sh[t - st] : 0;
        __syncthreads();
        sh[t] += x;
        __syncthreads();
    }
    if (i < NN) g_offG[i] = sh[t] - v;
    if (t == 1023) g_bsum[blockIdx.x] = sh[1023];
}

__global__ void k_scan2(int nb) {
    __shared__ int sh[128];
    int t = threadIdx.x;
    int v = (t < nb) ? g_bsum[t] : 0;
    sh[t] = v;
    __syncthreads();
    for (int st = 1; st < 128; st <<= 1) {
        int x = (t >= st) ? sh[t - st] : 0;
        __syncthreads();
        sh[t] += x;
        __syncthreads();
    }
    if (t < nb) g_bsum[t] = sh[t] - v;
}

__global__ void k_scan3() {
    int i = blockIdx.x * 1024 + threadIdx.x;
    if (i < NN) {
        int o = g_offG[i] + g_bsum[blockIdx.x];
        g_offG[i] = o;
        g_curG[i] = o;
    }
}

__global__ void k_place() {
    int i = blockIdx.x * blockDim.x + threadIdx.x;
    if (i >= E) return;
    int p = atomicAdd(&g_curG[g_dst[i]], 1);
    if ((unsigned)p < E) g_csrG_src[p] = g_src[i];
}

// ------------------- bf16-split tensor-core GEMM + bias + leaky + fused l2norm -------------------
#define GB 313   // divup(NI,128)
__global__ __launch_bounds__(256) void k_gemm_both(
    const float* __restrict__ A0, const float* __restrict__ B0, const float* __restrict__ bias0,
    const float* __restrict__ A1, const float* __restrict__ B1, const float* __restrict__ bias1)
{
    int bid = blockIdx.x;
    int mod = (bid >= GB) ? 1 : 0;
    int mb  = mod ? (bid - GB) : bid;
    const float* A    = mod ? A1 : A0;
    const float* Bm   = mod ? B1 : B0;
    const float* bias = mod ? bias1 : bias0;
    int K = mod ? 384 : 2048;

    float* C = g_xm + (size_t)mod * NN * D + (size_t)NU * D;
    __shared__ __nv_bfloat16 sAh[128][40];
    __shared__ __nv_bfloat16 sAl[128][40];
    __shared__ __nv_bfloat16 sBh[32][72];
    __shared__ __nv_bfloat16 sBl[32][72];
    __shared__ float sSum[128][2];

    int t    = threadIdx.x;
    int lane = t & 31;
    int wid  = t >> 5;
    int mw   = (wid & 3) * 32;
    int nw   = (wid >> 2) * 32;
    int m0   = mb * 128;

    int la_r = t >> 3;
    int la_c = (t & 7) * 4;
    int lb_k = t >> 4;
    int lb_c = (t & 15) * 4;

    int lr  = lane & 7;
    int sel = lane >> 3;

    float c[2][4][4];
    #pragma unroll
    for (int i = 0; i < 2; i++)
        #pragma unroll
        for (int j = 0; j < 4; j++)
            #pragma unroll
            for (int q = 0; q < 4; q++) c[i][j][q] = 0.f;

    float4 avr[4], bvr[2];
    #pragma unroll
    for (int p = 0; p < 4; p++) {
        int gm = m0 + la_r + p * 32;
        avr[p] = make_float4(0.f, 0.f, 0.f, 0.f);
        if (gm < NI) avr[p] = *(const float4*)&A[(size_t)gm * K + la_c];
    }
    #pragma unroll
    for (int p = 0; p < 2; p++)
        bvr[p] = *(const float4*)&Bm[(size_t)(lb_k + p * 16) * 64 + lb_c];

    for (int kt = 0; kt < K; kt += 32) {
        #pragma unroll
        for (int p = 0; p < 4; p++) {
            int m = la_r + p * 32;
            float vv[4] = {avr[p].x, avr[p].y, avr[p].z, avr[p].w};
            #pragma unroll
            for (int j = 0; j < 4; j++) {
                __nv_bfloat16 h, l;
                cvt_split(vv[j], h, l);
                sAh[m][la_c + j] = h;
                sAl[m][la_c + j] = l;
            }
        }
        #pragma unroll
        for (int p = 0; p < 2; p++) {
            int k = lb_k + p * 16;
            float vv[4] = {bvr[p].x, bvr[p].y, bvr[p].z, bvr[p].w};
            #pragma unroll
            for (int j = 0; j < 4; j++) {
                __nv_bfloat16 h, l;
                cvt_split(vv[j], h, l);
                sBh[k][lb_c + j] = h;
                sBl[k][lb_c + j] = l;
            }
        }
        __syncthreads();

        if (kt + 32 < K) {
            #pragma unroll
            for (int p = 0; p < 4; p++) {
                int gm = m0 + la_r + p * 32;
                avr[p] = make_float4(0.f, 0.f, 0.f, 0.f);
                if (gm < NI) avr[p] = *(const float4*)&A[(size_t)gm * K + kt + 32 + la_c];
            }
            #pragma unroll
            for (int p = 0; p < 2; p++)
                bvr[p] = *(const float4*)&Bm[(size_t)(kt + 32 + lb_k + p * 16) * 64 + lb_c];
        }

        #pragma unroll
        for (int kk = 0; kk < 32; kk += 16) {
            uint bh[4][2], bl[4][2];
            #pragma unroll
            for (int np = 0; np < 2; np++) {
                int brow = kk + lr + (sel & 1) * 8;
                int bcol = nw + np * 16 + (sel >> 1) * 8;
                uint ad = smem_u32(&sBh[brow][bcol]);
                ldsm4t(bh[np*2][0], bh[np*2][1], bh[np*2+1][0], bh[np*2+1][1], ad);
                ad = smem_u32(&sBl[brow][bcol]);
                ldsm4t(bl[np*2][0], bl[np*2][1], bl[np*2+1][0], bl[np*2+1][1], ad);
            }
            #pragma unroll
            for (int mt = 0; mt < 2; mt++) {
                int arow = mw + mt * 16 + lr + (sel & 1) * 8;
                int acol = kk + (sel >> 1) * 8;
                uint ah[4], al[4];
                uint ad = smem_u32(&sAh[arow][acol]);
                ldsm4(ah[0], ah[1], ah[2], ah[3], ad);
                ad = smem_u32(&sAl[arow][acol]);
                ldsm4(al[0], al[1], al[2], al[3], ad);
                #pragma unroll
                for (int nt = 0; nt < 4; nt++) {
                    mma_bf16(c[mt][nt], ah, bh[nt]);
                    mma_bf16(c[mt][nt], al, bh[nt]);
                    mma_bf16(c[mt][nt], ah, bl[nt]);
                }
            }
        }
        __syncthreads();
    }

    // ---- epilogue: bias + leaky, then fused row l2norm (cross-warp via sSum) ----
    int g  = lane >> 2;
    int q4 = lane & 3;

    // bias + leaky into c
    #pragma unroll
    for (int mt = 0; mt < 2; mt++)
        #pragma unroll
        for (int nt = 0; nt < 4; nt++) {
            int col = nw + nt * 8 + 2 * q4;
            float b0 = bias[col], b1 = bias[col + 1];
            c[mt][nt][0] = lrelu(c[mt][nt][0] + b0);
            c[mt][nt][1] = lrelu(c[mt][nt][1] + b1);
            c[mt][nt][2] = lrelu(c[mt][nt][2] + b0);
            c[mt][nt][3] = lrelu(c[mt][nt][3] + b1);
        }

    // partial row sumsq: reduce over this warp's 32 cols (4 nt x 2 cols x 4 q-lanes)
    #pragma unroll
    for (int mt = 0; mt < 2; mt++)
        #pragma unroll
        for (int half = 0; half < 2; half++) {
            float p = 0.f;
            #pragma unroll
            for (int nt = 0; nt < 4; nt++) {
                float v0 = c[mt][nt][half * 2], v1 = c[mt][nt][half * 2 + 1];
                p += v0 * v0 + v1 * v1;
            }
            p += __shfl_xor_sync(0xffffffffu, p, 1);
            p += __shfl_xor_sync(0xffffffffu, p, 2);
            if (q4 == 0) sSum[mw + mt * 16 + half * 8 + g][nw >> 5] = p;
        }
    __syncthreads();

    #pragma unroll
    for (int mt = 0; mt < 2; mt++) {
        #pragma unroll
        for (int half = 0; half < 2; half++) {
            int lrow = mw + mt * 16 + half * 8 + g;
            int gr = m0 + lrow;
            if (gr < NI) {
                float ssq = sSum[lrow][0] + sSum[lrow][1];
                float inv = rsqrtf(fmaxf(ssq, 1e-24f));
                float* crow = C + (size_t)gr * 64;
                #pragma unroll
                for (int nt = 0; nt < 4; nt++) {
                    int col = nw + nt * 8 + 2 * q4;
                    float v0 = c[mt][nt][half * 2]     * inv;
                    float v1 = c[mt][nt][half * 2 + 1] * inv;
                    *(float2*)&crow[col] = make_float2(v0, v1);
                }
            }
        }
    }
}

// merged l2norm: y=0 -> pref_v, y=1 -> pref_t, y=2 -> g_hx slot0 = l2norm(id_emb).
__global__ void k_l2norm_all(const float* __restrict__ in0, const float* __restrict__ in1,
                             const float* __restrict__ in2) {
    int which = blockIdx.y;
    int rows = (which == 2) ? NN : NU;
    int row = blockIdx.x * 8 + (threadIdx.x >> 5);
    if (row >= rows) return;
    const float* in = (which == 0) ? in0 : (which == 1) ? in1 : in2;
    float* outp = (which == 2) ? (g_hx + (size_t)row * D)
                               : (g_xm + (size_t)which * NN * D + (size_t)row * D);
    int lane = threadIdx.x & 31;
    float a = in[(size_t)row * 64 + lane];
    float b = in[(size_t)row * 64 + 32 + lane];
    float ss = a * a + b * b;
    #pragma unroll
    for (int o = 16; o; o >>= 1) ss += __shfl_xor_sync(0xffffffffu, ss, o);
    float inv = rsqrtf(fmaxf(ss, 1e-24f));
    outp[lane]      = a * inv;
    outp[32 + lane] = b * inv;
}

// ------------------- GAT (single-pass softmax, chunked MLP=8 gather) -------------------
__global__ void k_gat_node(int nNodes, int mode, float* __restrict__ out) {
    int n = blockIdx.x * 8 + (threadIdx.x >> 5);
    if (n >= nNodes) return;
    int mod = blockIdx.y;
    float* xbase = g_xm + (size_t)mod * NN * D;
    int lane = threadIdx.x & 31;
    int beg = g_offG[n];
    int end = beg + g_degG[n];

    float2 xd = *(const float2*)&xbase[(size_t)n * D + lane * 2];

    float* ebuf = g_e + (size_t)mod * E;
    float s = 0.f, ax = 0.f, ay = 0.f;
    for (int p0 = beg; p0 < end; p0 += 8) {
        int cnt = end - p0;
        if (cnt > 8) cnt = 8;
        float2 vv[8];
        int sidx[8];
        #pragma unroll
        for (int j = 0; j < 8; j++)
            if (j < cnt) sidx[j] = g_csrG_src[p0 + j];
        #pragma unroll
        for (int j = 0; j < 8; j++)
            if (j < cnt) vv[j] = *(const float2*)&xbase[(size_t)sidx[j] * D + lane * 2];
        #pragma unroll
        for (int j = 0; j < 8; j++) {
            if (j < cnt) {
                float dt = xd.x * vv[j].x + xd.y * vv[j].y;
                #pragma unroll
                for (int o = 16; o; o >>= 1) dt += __shfl_xor_sync(0xffffffffu, dt, o);
                float ex = __expf(dt);
                if (mode == 1 && lane == 0) ebuf[p0 + j] = ex;
                s  += ex;
                ax += ex * vv[j].x;
                ay += ex * vv[j].y;
            }
        }
    }

    if (mode == 0) {
        float invs = 1.f / (s + 1e-16f);
        float nx = xd.x + ax * invs;
        float ny = xd.y + ay * invs;
        float ss = nx * nx + ny * ny;
        #pragma unroll
        for (int o = 16; o; o >>= 1) ss += __shfl_xor_sync(0xffffffffu, ss, o);
        float inv = rsqrtf(fmaxf(ss, 1e-24f));
        xbase[(size_t)n * D + lane * 2]     = nx * inv;
        xbase[(size_t)n * D + lane * 2 + 1] = ny * inv;
    } else {
        float inv2 = 1.f / (2.f * s + 1e-16f);
        float* alpha = g_alpha + (size_t)mod * E;
        __syncwarp();
        for (int p = beg + lane; p < end; p += 32)
            alpha[p] = ebuf[p] * inv2;
        float sc = inv2 + inv2;
        int c = lane * 2;
        out[(size_t)n * OD + 64 + mod * 64 + c]     = xd.x + lrelu(ax * sc);
        out[(size_t)n * OD + 64 + mod * 64 + c + 1] = xd.y + lrelu(ay * sc);
    }
}

// SAGE gather (chunked MLP=8). layer 1 computes g_wc inline; layer 2 reads g_wc.
__global__ void k_sage_node(int layer, const float* __restrict__ conf, float* __restrict__ out) {
    int n = blockIdx.x * 8 + (threadIdx.x >> 5);
    if (n >= NN) return;
    const float* xin = g_hx + (size_t)(layer - 1) * NN * D;
    int lane = threadIdx.x & 31;
    int beg = g_offG[n];
    int cnt0 = g_degG[n];
    int end = beg + cnt0;
    float ax = 0.f, ay = 0.f;

    for (int p0 = beg; p0 < end; p0 += 8) {
        int cnt = end - p0;
        if (cnt > 8) cnt = 8;
        int sidx[8];
        float w[8];
        #pragma unroll
        for (int j = 0; j < 8; j++)
            if (j < cnt) sidx[j] = g_csrG_src[p0 + j];
        if (layer == 1) {
            #pragma unroll
            for (int j = 0; j < 8; j++)
                if (j < cnt) {
                    float wv = g_alpha[p0 + j];
                    float wt = g_alpha[E + p0 + j];
                    float2 cf = *(const float2*)&conf[2 * sidx[j]];
                    w[j] = fmaxf(fmaxf(wv * cf.x, wt * cf.y), 0.f);
                    if (lane == 0) g_wc[p0 + j] = w[j];
                }
        } else {
            #pragma unroll
            for (int j = 0; j < 8; j++)
                if (j < cnt) w[j] = g_wc[p0 + j];
        }
        float2 vv[8];
        #pragma unroll
        for (int j = 0; j < 8; j++)
            if (j < cnt && w[j] != 0.f)
                vv[j] = *(const float2*)&xin[(size_t)sidx[j] * D + lane * 2];
        #pragma unroll
        for (int j = 0; j < 8; j++)
            if (j < cnt && w[j] != 0.f) {
                ax += w[j] * vv[j].x;
                ay += w[j] * vv[j].y;
            }
    }

    float invd = 1.f / fmaxf((float)cnt0, 1.f);
    float hx = lrelu(ax * invd), hy = lrelu(ay * invd);
    int c = lane * 2;
    if (layer == 1) {
        g_hx[(size_t)NN * D + (size_t)n * D + c]     = hx;
        g_hx[(size_t)NN * D + (size_t)n * D + c + 1] = hy;
    } else {
        size_t b = (size_t)n * D + c;
        out[(size_t)n * OD + c]     = g_hx[b]     + g_hx[(size_t)NN * D + b]     + hx;
        out[(size_t)n * OD + c + 1] = g_hx[b + 1] + g_hx[(size_t)NN * D + b + 1] + hy;
    }
}

// ------------------- launch -------------------
extern "C" void kernel_launch(void* const* d_in, const int* in_sizes, int n_in,
                              void* d_out, int out_size) {
    const void* ei = nullptr;
    const float *v_feat = 0, *t_feat = 0, *pref_v = 0, *pref_t = 0;
    const float *W_v = 0, *b_v = 0, *W_t = 0, *b_t = 0, *id_emb = 0, *conf = 0;
    for (int i = 0; i < n_in; i++) {
        long long sz = in_sizes[i];
        const void* p = d_in[i];
        switch (sz) {
            case 2000000LL:  ei = p; break;
            case 81920000LL: v_feat = (const float*)p; break;
            case 15360000LL: t_feat = (const float*)p; break;
            case 3200000LL:  if (!pref_v) pref_v = (const float*)p; else pref_t = (const float*)p; break;
            case 131072LL:   W_v = (const float*)p; break;
            case 24576LL:    W_t = (const float*)p; break;
            case 64LL:       if (!b_v) b_v = (const float*)p; else b_t = (const float*)p; break;
            case 5760000LL:  id_emb = (const float*)p; break;
            case 180000LL:   conf = (const float*)p; break;
            default: break;
        }
    }
    float* out = (float*)d_out;

    const int B = 256;
    const int nScanB = divup(NN, 1024);
    dim3 gU(divup(NU, 8), 2);
    dim3 gA(divup(NN, 8), 2);
    dim3 gN(divup(NN, 8), 3);

    // graph construction
    k_zero_sniff<<<divup(NN, B), B>>>((const int*)ei);
    k_build<<<divup(E, B), B>>>(ei);
    k_scan1<<<nScanB, 1024>>>();
    k_scan2<<<1, 128>>>(nScanB);
    k_scan3<<<nScanB, 1024>>>();
    k_place<<<divup(E, B), B>>>();

    // content GEMMs (fused bias+leaky+l2norm) + all remaining l2norms in one launch
    k_gemm_both<<<2 * GB, 256>>>(v_feat, W_v, b_v, t_feat, W_t, b_t);
    k_l2norm_all<<<gN, 256>>>(pref_v, pref_t, id_emb);

    for (int it = 0; it < 3; it++)
        k_gat_node<<<gU, 256>>>(NU, 0, nullptr);
    k_gat_node<<<gA, 256>>>(NN, 1, out);

    // SAGE (layer 1 computes edge weights inline)
    k_sage_node<<<divup(NN, 8), 256>>>(1, conf, nullptr);
    k_sage_node<<<divup(NN, 8), 256>>>(2, conf, out);
}

// round 17
// speedup vs baseline: 1.2102x; 1.2102x over previous
#include <cuda_runtime.h>
#include <cuda_bf16.h>
#include <math.h>

#define NU 50000
#define NI 40000
#define NN 90000
#define D  64
#define EH 500000
#define E  1000000
#define OD 192

typedef unsigned int uint;

// ------------------- scratch (static device globals; no allocation) -------------------
__device__ int   g_is64;
__device__ int   g_src[E];
__device__ int   g_dst[E];
__device__ int   g_degG[NN];
__device__ int   g_offG[NN];
__device__ int   g_curG[NN];
__device__ int   g_bsum[128];
__device__ int   g_csrG_src[E];
__device__ float g_e[2 * E];
__device__ float g_alpha[2 * E];
__device__ float g_wc[E];
__device__ __align__(16) float g_xm[2 * NN * D];
__device__ __align__(16) float g_hx[2 * NN * D];

__device__ __forceinline__ float lrelu(float v) { return v >= 0.f ? v : 0.01f * v; }
static inline int divup(int a, int b) { return (a + b - 1) / b; }

// ------------------- tensor helpers -------------------
__device__ __forceinline__ uint smem_u32(const void* p) {
    return (uint)__cvta_generic_to_shared(p);
}
__device__ __forceinline__ void ldsm4(uint& r0, uint& r1, uint& r2, uint& r3, uint addr) {
    asm volatile("ldmatrix.sync.aligned.m8n8.x4.shared.b16 {%0,%1,%2,%3},[%4];"
        : "=r"(r0), "=r"(r1), "=r"(r2), "=r"(r3) : "r"(addr));
}
__device__ __forceinline__ void ldsm4t(uint& r0, uint& r1, uint& r2, uint& r3, uint addr) {
    asm volatile("ldmatrix.sync.aligned.m8n8.x4.trans.shared.b16 {%0,%1,%2,%3},[%4];"
        : "=r"(r0), "=r"(r1), "=r"(r2), "=r"(r3) : "r"(addr));
}
__device__ __forceinline__ void mma_bf16(float* c, const uint* a, const uint* b) {
    asm volatile("mma.sync.aligned.m16n8k16.row.col.f32.bf16.bf16.f32 "
        "{%0,%1,%2,%3},{%4,%5,%6,%7},{%8,%9},{%0,%1,%2,%3};"
        : "+f"(c[0]), "+f"(c[1]), "+f"(c[2]), "+f"(c[3])
        : "r"(a[0]), "r"(a[1]), "r"(a[2]), "r"(a[3]), "r"(b[0]), "r"(b[1]));
}
__device__ __forceinline__ void cvt_split(float v, __nv_bfloat16& h, __nv_bfloat16& l) {
    h = __float2bfloat16_rn(v);
    l = __float2bfloat16_rn(v - __bfloat162float(h));
}

// ------------------- graph construction -------------------
// zero degrees; block 0 warp 0 also sniffs the edge dtype.
__global__ void k_zero_sniff(const int* __restrict__ ei32) {
    int i = blockIdx.x * blockDim.x + threadIdx.x;
    if (i < NN) g_degG[i] = 0;
    if (blockIdx.x == 0 && threadIdx.x < 32) {
        int lane = threadIdx.x;
        int nz = 0;
        for (int k = lane; k < 512; k += 32)
            if (ei32[2 * k + 1] != 0) nz++;
        #pragma unroll
        for (int o = 16; o; o >>= 1) nz += __shfl_xor_sync(0xffffffffu, nz, o);
        if (lane == 0) g_is64 = (nz == 0) ? 1 : 0;
    }
}

__global__ void k_build(const void* __restrict__ eiRaw) {
    int i = blockIdx.x * blockDim.x + threadIdx.x;
    if (i >= E) return;
    int s, d;
    if (g_is64) {
        const long long* e64 = (const long long*)eiRaw;
        s = (int)e64[i];
        d = (int)e64[E + i];
    } else {
        const int* e32 = (const int*)eiRaw;
        s = e32[i];
        d = e32[E + i];
    }
    if ((unsigned)s >= NN) s = 0;
    if ((unsigned)d >= NN) d = 0;
    g_src[i] = s;
    g_dst[i] = d;
    atomicAdd(&g_degG[d], 1);
}

__global__ void k_scan1() {
    __shared__ int sh[1024];
    int t = threadIdx.x;
    int i = blockIdx.x * 1024 + t;
    int v = (i < NN) ? g_degG[i] : 0;
    sh[t] = v;
    __syncthreads();
    for (int st = 1; st < 1024; st <<= 1) {
        int x = (t >= st) ? sh[t - st] : 0;
        __syncthreads();
        sh[t] += x;
        __syncthreads();
    }
    if (i < NN) g_offG[i] = sh[t] - v;
    if (t == 1023) g_bsum[blockIdx.x] = sh[1023];
}

__global__ void k_scan2(int nb) {
    __shared__ int sh[128];
    int t = threadIdx.x;
    int v = (t < nb) ? g_bsum[t] : 0;
    sh[t] = v;
    __syncthreads();
    for (int st = 1; st < 128; st <<= 1) {
        int x = (t >= st) ? sh[t - st] : 0;
        __syncthreads();
        sh[t] += x;
        __syncthreads();
    }
    if (t < nb) g_bsum[t] = sh[t] - v;
}

__global__ void k_scan3() {
    int i = blockIdx.x * 1024 + threadIdx.x;
    if (i < NN) {
        int o = g_offG[i] + g_bsum[blockIdx.x];
        g_offG[i] = o;
        g_curG[i] = o;
    }
}

__global__ void k_place() {
    int i = blockIdx.x * blockDim.x + threadIdx.x;
    if (i >= E) return;
    int p = atomicAdd(&g_curG[g_dst[i]], 1);
    if ((unsigned)p < E) g_csrG_src[p] = g_src[i];
}

// ------------------- bf16-split tensor-core GEMM + bias + leaky + fused l2norm -------------------
#define GB 313   // divup(NI,128)
__global__ __launch_bounds__(256) void k_gemm_both(
    const float* __restrict__ A0, const float* __restrict__ B0, const float* __restrict__ bias0,
    const float* __restrict__ A1, const float* __restrict__ B1, const float* __restrict__ bias1)
{
    int bid = blockIdx.x;
    int mod = (bid >= GB) ? 1 : 0;
    int mb  = mod ? (bid - GB) : bid;
    const float* A    = mod ? A1 : A0;
    const float* Bm   = mod ? B1 : B0;
    const float* bias = mod ? bias1 : bias0;
    int K = mod ? 384 : 2048;

    float* C = g_xm + (size_t)mod * NN * D + (size_t)NU * D;
    __shared__ __nv_bfloat16 sAh[128][40];
    __shared__ __nv_bfloat16 sAl[128][40];
    __shared__ __nv_bfloat16 sBh[32][72];
    __shared__ __nv_bfloat16 sBl[32][72];
    __shared__ float sSum[128][2];

    int t    = threadIdx.x;
    int lane = t & 31;
    int wid  = t >> 5;
    int mw   = (wid & 3) * 32;
    int nw   = (wid >> 2) * 32;
    int m0   = mb * 128;

    int la_r = t >> 3;
    int la_c = (t & 7) * 4;
    int lb_k = t >> 4;
    int lb_c = (t & 15) * 4;

    int lr  = lane & 7;
    int sel = lane >> 3;

    float c[2][4][4];
    #pragma unroll
    for (int i = 0; i < 2; i++)
        #pragma unroll
        for (int j = 0; j < 4; j++)
            #pragma unroll
            for (int q = 0; q < 4; q++) c[i][j][q] = 0.f;

    float4 avr[4], bvr[2];
    #pragma unroll
    for (int p = 0; p < 4; p++) {
        int gm = m0 + la_r + p * 32;
        avr[p] = make_float4(0.f, 0.f, 0.f, 0.f);
        if (gm < NI) avr[p] = *(const float4*)&A[(size_t)gm * K + la_c];
    }
    #pragma unroll
    for (int p = 0; p < 2; p++)
        bvr[p] = *(const float4*)&Bm[(size_t)(lb_k + p * 16) * 64 + lb_c];

    for (int kt = 0; kt < K; kt += 32) {
        #pragma unroll
        for (int p = 0; p < 4; p++) {
            int m = la_r + p * 32;
            float vv[4] = {avr[p].x, avr[p].y, avr[p].z, avr[p].w};
            #pragma unroll
            for (int j = 0; j < 4; j++) {
                __nv_bfloat16 h, l;
                cvt_split(vv[j], h, l);
                sAh[m][la_c + j] = h;
                sAl[m][la_c + j] = l;
            }
        }
        #pragma unroll
        for (int p = 0; p < 2; p++) {
            int k = lb_k + p * 16;
            float vv[4] = {bvr[p].x, bvr[p].y, bvr[p].z, bvr[p].w};
            #pragma unroll
            for (int j = 0; j < 4; j++) {
                __nv_bfloat16 h, l;
                cvt_split(vv[j], h, l);
                sBh[k][lb_c + j] = h;
                sBl[k][lb_c + j] = l;
            }
        }
        __syncthreads();

        if (kt + 32 < K) {
            #pragma unroll
            for (int p = 0; p < 4; p++) {
                int gm = m0 + la_r + p * 32;
                avr[p] = make_float4(0.f, 0.f, 0.f, 0.f);
                if (gm < NI) avr[p] = *(const float4*)&A[(size_t)gm * K + kt + 32 + la_c];
            }
            #pragma unroll
            for (int p = 0; p < 2; p++)
                bvr[p] = *(const float4*)&Bm[(size_t)(kt + 32 + lb_k + p * 16) * 64 + lb_c];
        }

        #pragma unroll
        for (int kk = 0; kk < 32; kk += 16) {
            uint bh[4][2], bl[4][2];
            #pragma unroll
            for (int np = 0; np < 2; np++) {
                int brow = kk + lr + (sel & 1) * 8;
                int bcol = nw + np * 16 + (sel >> 1) * 8;
                uint ad = smem_u32(&sBh[brow][bcol]);
                ldsm4t(bh[np*2][0], bh[np*2][1], bh[np*2+1][0], bh[np*2+1][1], ad);
                ad = smem_u32(&sBl[brow][bcol]);
                ldsm4t(bl[np*2][0], bl[np*2][1], bl[np*2+1][0], bl[np*2+1][1], ad);
            }
            #pragma unroll
            for (int mt = 0; mt < 2; mt++) {
                int arow = mw + mt * 16 + lr + (sel & 1) * 8;
                int acol = kk + (sel >> 1) * 8;
                uint ah[4], al[4];
                uint ad = smem_u32(&sAh[arow][acol]);
                ldsm4(ah[0], ah[1], ah[2], ah[3], ad);
                ad = smem_u32(&sAl[arow][acol]);
                ldsm4(al[0], al[1], al[2], al[3], ad);
                #pragma unroll
                for (int nt = 0; nt < 4; nt++) {
                    mma_bf16(c[mt][nt], ah, bh[nt]);
                    mma_bf16(c[mt][nt], al, bh[nt]);
                    mma_bf16(c[mt][nt], ah, bl[nt]);
                }
            }
        }
        __syncthreads();
    }

    // ---- epilogue: bias + leaky, then fused row l2norm (cross-warp via sSum) ----
    int g  = lane >> 2;
    int q4 = lane & 3;

    #pragma unroll
    for (int mt = 0; mt < 2; mt++)
        #pragma unroll
        for (int nt = 0; nt < 4; nt++) {
            int col = nw + nt * 8 + 2 * q4;
            float b0 = bias[col], b1 = bias[col + 1];
            c[mt][nt][0] = lrelu(c[mt][nt][0] + b0);
            c[mt][nt][1] = lrelu(c[mt][nt][1] + b1);
            c[mt][nt][2] = lrelu(c[mt][nt][2] + b0);
            c[mt][nt][3] = lrelu(c[mt][nt][3] + b1);
        }

    #pragma unroll
    for (int mt = 0; mt < 2; mt++)
        #pragma unroll
        for (int half = 0; half < 2; half++) {
            float p = 0.f;
            #pragma unroll
            for (int nt = 0; nt < 4; nt++) {
                float v0 = c[mt][nt][half * 2], v1 = c[mt][nt][half * 2 + 1];
                p += v0 * v0 + v1 * v1;
            }
            p += __shfl_xor_sync(0xffffffffu, p, 1);
            p += __shfl_xor_sync(0xffffffffu, p, 2);
            if (q4 == 0) sSum[mw + mt * 16 + half * 8 + g][nw >> 5] = p;
        }
    __syncthreads();

    #pragma unroll
    for (int mt = 0; mt < 2; mt++) {
        #pragma unroll
        for (int half = 0; half < 2; half++) {
            int lrow = mw + mt * 16 + half * 8 + g;
            int gr = m0 + lrow;
            if (gr < NI) {
                float ssq = sSum[lrow][0] + sSum[lrow][1];
                float inv = rsqrtf(fmaxf(ssq, 1e-24f));
                float* crow = C + (size_t)gr * 64;
                #pragma unroll
                for (int nt = 0; nt < 4; nt++) {
                    int col = nw + nt * 8 + 2 * q4;
                    float v0 = c[mt][nt][half * 2]     * inv;
                    float v1 = c[mt][nt][half * 2 + 1] * inv;
                    *(float2*)&crow[col] = make_float2(v0, v1);
                }
            }
        }
    }
}

// merged l2norm: y=0 -> pref_v, y=1 -> pref_t, y=2 -> g_hx slot0 = l2norm(id_emb).
__global__ void k_l2norm_all(const float* __restrict__ in0, const float* __restrict__ in1,
                             const float* __restrict__ in2) {
    int which = blockIdx.y;
    int rows = (which == 2) ? NN : NU;
    int row = blockIdx.x * 8 + (threadIdx.x >> 5);
    if (row >= rows) return;
    const float* in = (which == 0) ? in0 : (which == 1) ? in1 : in2;
    float* outp = (which == 2) ? (g_hx + (size_t)row * D)
                               : (g_xm + (size_t)which * NN * D + (size_t)row * D);
    int lane = threadIdx.x & 31;
    float a = in[(size_t)row * 64 + lane];
    float b = in[(size_t)row * 64 + 32 + lane];
    float ss = a * a + b * b;
    #pragma unroll
    for (int o = 16; o; o >>= 1) ss += __shfl_xor_sync(0xffffffffu, ss, o);
    float inv = rsqrtf(fmaxf(ss, 1e-24f));
    outp[lane]      = a * inv;
    outp[32 + lane] = b * inv;
}

// ------------------- GAT (single-pass softmax, chunked MLP=4 gather) -------------------
__global__ void k_gat_node(int nNodes, int mode, float* __restrict__ out) {
    int n = blockIdx.x * 8 + (threadIdx.x >> 5);
    if (n >= nNodes) return;
    int mod = blockIdx.y;
    float* xbase = g_xm + (size_t)mod * NN * D;
    int lane = threadIdx.x & 31;
    int beg = g_offG[n];
    int end = beg + g_degG[n];

    float2 xd = *(const float2*)&xbase[(size_t)n * D + lane * 2];

    float* ebuf = g_e + (size_t)mod * E;
    float s = 0.f, ax = 0.f, ay = 0.f;
    for (int p0 = beg; p0 < end; p0 += 4) {
        int cnt = end - p0;
        if (cnt > 4) cnt = 4;
        float2 vv[4];
        int sidx[4];
        #pragma unroll
        for (int j = 0; j < 4; j++)
            if (j < cnt) sidx[j] = g_csrG_src[p0 + j];
        #pragma unroll
        for (int j = 0; j < 4; j++)
            if (j < cnt) vv[j] = *(const float2*)&xbase[(size_t)sidx[j] * D + lane * 2];
        #pragma unroll
        for (int j = 0; j < 4; j++) {
            if (j < cnt) {
                float dt = xd.x * vv[j].x + xd.y * vv[j].y;
                #pragma unroll
                for (int o = 16; o; o >>= 1) dt += __shfl_xor_sync(0xffffffffu, dt, o);
                float ex = __expf(dt);
                if (mode == 1 && lane == 0) ebuf[p0 + j] = ex;
                s  += ex;
                ax += ex * vv[j].x;
                ay += ex * vv[j].y;
            }
        }
    }

    if (mode == 0) {
        float invs = 1.f / (s + 1e-16f);
        float nx = xd.x + ax * invs;
        float ny = xd.y + ay * invs;
        float ss = nx * nx + ny * ny;
        #pragma unroll
        for (int o = 16; o; o >>= 1) ss += __shfl_xor_sync(0xffffffffu, ss, o);
        float inv = rsqrtf(fmaxf(ss, 1e-24f));
        xbase[(size_t)n * D + lane * 2]     = nx * inv;
        xbase[(size_t)n * D + lane * 2 + 1] = ny * inv;
    } else {
        float inv2 = 1.f / (2.f * s + 1e-16f);
        float* alpha = g_alpha + (size_t)mod * E;
        __syncwarp();
        for (int p = beg + lane; p < end; p += 32)
            alpha[p] = ebuf[p] * inv2;
        float sc = inv2 + inv2;
        int c = lane * 2;
        out[(size_t)n * OD + 64 + mod * 64 + c]     = xd.x + lrelu(ax * sc);
        out[(size_t)n * OD + 64 + mod * 64 + c + 1] = xd.y + lrelu(ay * sc);
    }
}

// SAGE gather (chunked MLP=4). layer 1 computes g_wc inline; layer 2 reads g_wc.
__global__ void k_sage_node(int layer, const float* __restrict__ conf, float* __restrict__ out) {
    int n = blockIdx.x * 8 + (threadIdx.x >> 5);
    if (n >= NN) return;
    const float* xin = g_hx + (size_t)(layer - 1) * NN * D;
    int lane = threadIdx.x & 31;
    int beg = g_offG[n];
    int cnt0 = g_degG[n];
    int end = beg + cnt0;
    float ax = 0.f, ay = 0.f;

    for (int p0 = beg; p0 < end; p0 += 4) {
        int cnt = end - p0;
        if (cnt > 4) cnt = 4;
        int sidx[4];
        float w[4];
        #pragma unroll
        for (int j = 0; j < 4; j++)
            if (j < cnt) sidx[j] = g_csrG_src[p0 + j];
        if (layer == 1) {
            #pragma unroll
            for (int j = 0; j < 4; j++)
                if (j < cnt) {
                    float wv = g_alpha[p0 + j];
                    float wt = g_alpha[E + p0 + j];
                    float2 cf = *(const float2*)&conf[2 * sidx[j]];
                    w[j] = fmaxf(fmaxf(wv * cf.x, wt * cf.y), 0.f);
                    if (lane == 0) g_wc[p0 + j] = w[j];
                }
        } else {
            #pragma unroll
            for (int j = 0; j < 4; j++)
                if (j < cnt) w[j] = g_wc[p0 + j];
        }
        float2 vv[4];
        #pragma unroll
        for (int j = 0; j < 4; j++)
            if (j < cnt && w[j] != 0.f)
                vv[j] = *(const float2*)&xin[(size_t)sidx[j] * D + lane * 2];
        #pragma unroll
        for (int j = 0; j < 4; j++)
            if (j < cnt && w[j] != 0.f) {
                ax += w[j] * vv[j].x;
                ay += w[j] * vv[j].y;
            }
    }

    float invd = 1.f / fmaxf((float)cnt0, 1.f);
    float hx = lrelu(ax * invd), hy = lrelu(ay * invd);
    int c = lane * 2;
    if (layer == 1) {
        g_hx[(size_t)NN * D + (size_t)n * D + c]     = hx;
        g_hx[(size_t)NN * D + (size_t)n * D + c + 1] = hy;
    } else {
        size_t b = (size_t)n * D + c;
        out[(size_t)n * OD + c]     = g_hx[b]     + g_hx[(size_t)NN * D + b]     + hx;
        out[(size_t)n * OD + c + 1] = g_hx[b + 1] + g_hx[(size_t)NN * D + b + 1] + hy;
    }
}

// ------------------- launch -------------------
extern "C" void kernel_launch(void* const* d_in, const int* in_sizes, int n_in,
                              void* d_out, int out_size) {
    const void* ei = nullptr;
    const float *v_feat = 0, *t_feat = 0, *pref_v = 0, *pref_t = 0;
    const float *W_v = 0, *b_v = 0, *W_t = 0, *b_t = 0, *id_emb = 0, *conf = 0;
    for (int i = 0; i < n_in; i++) {
        long long sz = in_sizes[i];
        const void* p = d_in[i];
        switch (sz) {
            case 2000000LL:  ei = p; break;
            case 81920000LL: v_feat = (const float*)p; break;
            case 15360000LL: t_feat = (const float*)p; break;
            case 3200000LL:  if (!pref_v) pref_v = (const float*)p; else pref_t = (const float*)p; break;
            case 131072LL:   W_v = (const float*)p; break;
            case 24576LL:    W_t = (const float*)p; break;
            case 64LL:       if (!b_v) b_v = (const float*)p; else b_t = (const float*)p; break;
            case 5760000LL:  id_emb = (const float*)p; break;
            case 180000LL:   conf = (const float*)p; break;
            default: break;
        }
    }
    float* out = (float*)d_out;

    const int B = 256;
    const int nScanB = divup(NN, 1024);
    dim3 gU(divup(NU, 8), 2);
    dim3 gA(divup(NN, 8), 2);
    dim3 gN(divup(NN, 8), 3);

    // graph construction
    k_zero_sniff<<<divup(NN, B), B>>>((const int*)ei);
    k_build<<<divup(E, B), B>>>(ei);
    k_scan1<<<nScanB, 1024>>>();
    k_scan2<<<1, 128>>>(nScanB);
    k_scan3<<<nScanB, 1024>>>();
    k_place<<<divup(E, B), B>>>();

    // content GEMMs (fused bias+leaky+l2norm) + all remaining l2norms in one launch
    k_gemm_both<<<2 * GB, 256>>>(v_feat, W_v, b_v, t_feat, W_t, b_t);
    k_l2norm_all<<<gN, 256>>>(pref_v, pref_t, id_emb);

    for (int it = 0; it < 3; it++)
        k_gat_node<<<gU, 256>>>(NU, 0, nullptr);
    k_gat_node<<<gA, 256>>>(NN, 1, out);

    // SAGE (layer 1 computes edge weights inline)
    k_sage_node<<<divup(NN, 8), 256>>>(1, conf, nullptr);
    k_sage_node<<<divup(NN, 8), 256>>>(2, conf, out);
}